// round 9
// baseline (speedup 1.0000x reference)
#include <cuda_runtime.h>
#include <cstdint>

// C51 categorical projection, round 9.
// Persistent blocks with a 3-stage TMA pipeline: while computing tile i in
// buffer cur, the TMA load of tile i+1 streams into buffer nxt and the bulk
// store of tile i-1 drains — DRAM never goes idle during compute/syncs
// (TMA progresses without warp issue). wait_group 1 before each new load
// guarantees the 2-iterations-old store of the target buffer has drained.
// Merge core unchanged: 2 threads/row, predicated streaming merge.

static constexpr int ATOMS_C    = 51;
static constexpr int ROWS       = 64;               // rows per tile
static constexpr int THREADS    = 128;              // 2 threads per row
static constexpr int TILE       = ROWS * ATOMS_C;   // 3264 floats
static constexpr int TILE_BYTES = TILE * 4;         // 13056
static constexpr int HALFN      = 26;               // atoms per half (incl. dummy)
static constexpr int NBUF       = 3;
static constexpr int V4         = TILE / 4;         // 816
static constexpr int V4FULL     = (V4 / THREADS) * THREADS;  // 768
static constexpr int V4REM      = V4 - V4FULL;               // 48
static constexpr int GRID       = 740;              // 148 SMs x 5 blocks

__global__ __launch_bounds__(THREADS) void c51_pipe_kernel(
    const float* __restrict__ g_reward,
    const float* __restrict__ g_dist,
    const int*   __restrict__ g_mask,
    float*       __restrict__ g_out,
    int n_tiles)
{
    __shared__ alignas(128) float s_tile[NBUF][TILE];
    __shared__ alignas(8)  unsigned long long s_mbar[NBUF];

    const int tid  = threadIdx.x;
    const int row  = tid & (ROWS - 1);
    const int half = tid >> 6;                     // 0: atoms 0..25, 1: 25..50

    uint32_t u_tile[NBUF], u_mbar[NBUF];
    #pragma unroll
    for (int b = 0; b < NBUF; ++b) {
        u_tile[b] = (uint32_t)__cvta_generic_to_shared(s_tile[b]);
        u_mbar[b] = (uint32_t)__cvta_generic_to_shared(&s_mbar[b]);
    }

    if (tid == 0) {
        #pragma unroll
        for (int b = 0; b < NBUF; ++b)
            asm volatile("mbarrier.init.shared::cta.b64 [%0], 1;" :: "r"(u_mbar[b]));
        asm volatile("fence.proxy.async.shared::cta;" ::: "memory");
    }
    __syncthreads();

    // ---- prologue: issue load of the first tile into buffer 0 ----
    const int t0 = blockIdx.x;
    if (tid == 0 && t0 < n_tiles) {
        asm volatile("mbarrier.arrive.expect_tx.shared::cta.b64 _, [%0], %1;"
                     :: "r"(u_mbar[0]), "r"(TILE_BYTES) : "memory");
        asm volatile(
            "cp.async.bulk.shared::cta.global.mbarrier::complete_tx::bytes "
            "[%0], [%1], %2, [%3];"
            :: "r"(u_tile[0]), "l"(g_dist + (long long)t0 * TILE),
               "r"(TILE_BYTES), "r"(u_mbar[0]) : "memory");
    }

    unsigned par = 0;                              // expected parity per buffer
    int cur = 0;
    for (int t = t0; t < n_tiles; t += GRID) {
        const int nxt = (cur == NBUF - 1) ? 0 : cur + 1;
        const int tn  = t + GRID;

        // ---- issue next load (buffer nxt was stored 2 iterations ago) ----
        if (tid == 0 && tn < n_tiles) {
            asm volatile("cp.async.bulk.wait_group 1;" ::: "memory");
            asm volatile("mbarrier.arrive.expect_tx.shared::cta.b64 _, [%0], %1;"
                         :: "r"(u_mbar[nxt]), "r"(TILE_BYTES) : "memory");
            asm volatile(
                "cp.async.bulk.shared::cta.global.mbarrier::complete_tx::bytes "
                "[%0], [%1], %2, [%3];"
                :: "r"(u_tile[nxt]), "l"(g_dist + (long long)tn * TILE),
                   "r"(TILE_BYTES), "r"(u_mbar[nxt]) : "memory");
        }

        // ---- per-row affine bin map (overlaps with the load wait) ----
        const int   r    = t * ROWS + row;
        const float rw   = __ldg(g_reward + r);
        const float mk   = (float)__ldg(g_mask + r);
        const float step = 0.99f * mk;
        float base = (rw + 10.0f) / 0.4f - 24.75f * mk;   // one div per row
        base = fmaf(step, (float)(half * 25), base);
        const float HI = 49.999996f;                       // largest f32 < 50

        // ---- wait for buffer cur's load (parity-tracked) ----
        {
            const uint32_t ph = (par >> cur) & 1u;
            uint32_t done;
            asm volatile(
                "{\n\t.reg .pred p;\n\t"
                "mbarrier.try_wait.parity.shared::cta.b64 p, [%1], %2;\n\t"
                "selp.b32 %0, 1, 0, p;\n\t}"
                : "=r"(done) : "r"(u_mbar[cur]), "r"(ph) : "memory");
            while (!done) {
                asm volatile(
                    "{\n\t.reg .pred p;\n\t"
                    "mbarrier.try_wait.parity.shared::cta.b64 p, [%1], %2, 0x989680;\n\t"
                    "selp.b32 %0, 1, 0, p;\n\t}"
                    : "=r"(done) : "r"(u_mbar[cur]), "r"(ph) : "memory");
            }
        }
        par ^= (1u << cur);

        float* __restrict__ tile = s_tile[cur];

        // ---- buffer own half-row into registers (stride 51, conflict-free) ----
        float d[HALFN];
        {
            const float* __restrict__ srow = tile + row * ATOMS_C + half * 25;
            #pragma unroll
            for (int j = 0; j < HALFN; ++j) d[j] = srow[j];
            if (half) d[0] = 0.0f;                 // dummy atom 25: zero weight
        }
        __syncthreads();                           // all reads before overwrite

        // ---- cooperative zero of buffer cur (reused in-place as output) ----
        float4* s4 = reinterpret_cast<float4*>(tile);
        const float4 z4 = make_float4(0.f, 0.f, 0.f, 0.f);
        #pragma unroll
        for (int i = 0; i < V4FULL / THREADS; ++i)
            s4[i * THREADS + tid] = z4;
        if (tid < V4REM) s4[V4FULL + tid] = z4;
        __syncthreads();

        // ---- streaming merge over this thread's 26 atoms ----
        float* __restrict__ orow = tile + row * ATOMS_C;

        float b    = fminf(fmaxf(base, 0.0f), HI);
        float curf = floorf(b);
        float* wptr = orow + (int)curf;            // single F2I per thread
        float acc1 = d[0] * (b - curf);            // half==1: d[0]=0 -> accs 0
        float acc0 = d[0] - acc1;

        #pragma unroll
        for (int j = 1; j < HALFN; ++j) {
            float bb = fmaf(step, (float)j, base); // FFMA, imm multiplier
            bb = fminf(fmaxf(bb, 0.0f), HI);
            const float lfn = floorf(bb);          // independent per atom
            const float bm  = bb - lfn;
            const float wu  = d[j] * bm;
            const float wl  = d[j] - wu;           // d*(lf+1-b)
            const bool adv  = (lfn != curf);       // l steps by exactly 0/1
            if (adv) *wptr = acc0;                 // @P STS, converged
            const float a0 = adv ? acc1 : acc0;
            acc0 = a0 + wl;
            const float t2 = acc1 + wu;
            acc1 = adv ? wu : t2;
            wptr = adv ? (wptr + 1) : wptr;
            curf = lfn;
        }
        if (half) {                                // B: plain final flush
            wptr[0] = acc0;                        // covers [cA, cB+1] once
            wptr[1] = acc1;
        }
        __syncthreads();
        if (!half) {                               // A: deferred carry, RMW add
            wptr[0] += acc0;                       // bins [cA, cA+1], B's region
            wptr[1] += acc1;
        }

        // ---- bulk store buffer cur (drains in the background) ----
        asm volatile("fence.proxy.async.shared::cta;" ::: "memory");
        __syncthreads();
        if (tid == 0) {
            asm volatile(
                "cp.async.bulk.global.shared::cta.bulk_group [%0], [%1], %2;"
                :: "l"(g_out + (long long)t * TILE), "r"(u_tile[cur]),
                   "r"(TILE_BYTES) : "memory");
            asm volatile("cp.async.bulk.commit_group;" ::: "memory");
        }
        cur = nxt;
    }
    if (tid == 0)
        asm volatile("cp.async.bulk.wait_group 0;" ::: "memory");
}

extern "C" void kernel_launch(void* const* d_in, const int* in_sizes, int n_in,
                              void* d_out, int out_size) {
    const float* reward = (const float*)d_in[0];   // batch_reward  [B] f32
    const float* dist   = (const float*)d_in[1];   // max_next_dist [B,51] f32
    // d_in[2] = supports (linspace) — folded into the affine map, unused
    const int*   mask   = (const int*)d_in[3];     // non_final_mask[B] i32
    float* out = (float*)d_out;                    // [B,51] f32

    const int B = in_sizes[0];                     // 1048576 (divisible by 64)
    const int n_tiles = B / ROWS;                  // 16384
    c51_pipe_kernel<<<GRID, THREADS>>>(reward, dist, mask, out, n_tiles);
}

// round 10
// speedup vs baseline: 1.0629x; 1.0629x over previous
#include <cuda_runtime.h>
#include <cstdint>

// C51 categorical projection, round 10.
// R7 structure (single in-place tile, TMA bulk in/out, 2 threads/row) plus a
// mask-based fast path: rows with non_final_mask==0 collapse to a single bin
// pair (out[l], out[l+1]) = (sum d)*(1-frac, frac). A block-level compaction
// permutes rows so warps are mask-uniform (except boundary warps), making the
// fast path divergence-free for ~3/4 of warps. ~45% fewer compute instrs.

static constexpr int ATOMS_C    = 51;
static constexpr int ROWS       = 64;               // rows per block
static constexpr int THREADS    = 128;              // 2 threads per row
static constexpr int TILE       = ROWS * ATOMS_C;   // 3264 floats
static constexpr int TILE_BYTES = TILE * 4;         // 13056
static constexpr int HALFN      = 26;               // atoms per half (incl. dummy)
static constexpr int V4         = TILE / 4;         // 816
static constexpr int V4FULL     = (V4 / THREADS) * THREADS;  // 768
static constexpr int V4REM      = V4 - V4FULL;               // 48

__global__ __launch_bounds__(THREADS) void c51_project_kernel(
    const float* __restrict__ g_reward,
    const float* __restrict__ g_dist,
    const int*   __restrict__ g_mask,
    float*       __restrict__ g_out)
{
    __shared__ alignas(128) float s_tile[TILE];
    __shared__ alignas(8)  unsigned long long s_mbar;
    __shared__ int   s_perm[ROWS];
    __shared__ float s_mkf[ROWS];
    __shared__ int   s_cnt[2];

    const int tid  = threadIdx.x;
    const int slot = tid & (ROWS - 1);
    const int half = tid >> 6;                      // 0: atoms 0..25, 1: 25..50
    const long long base_g = (long long)blockIdx.x * TILE;
    const int row0 = blockIdx.x * ROWS;

    const uint32_t u_tile = (uint32_t)__cvta_generic_to_shared(s_tile);
    const uint32_t u_mbar = (uint32_t)__cvta_generic_to_shared(&s_mbar);

    // ---- init mbarrier + partition counters ----
    if (tid == 0) {
        asm volatile("mbarrier.init.shared::cta.b64 [%0], 1;" :: "r"(u_mbar));
        asm volatile("fence.proxy.async.shared::cta;" ::: "memory");
        s_cnt[0] = 0;
        s_cnt[1] = ROWS - 1;
    }
    __syncthreads();

    // ---- TMA bulk load: GMEM -> SMEM ----
    if (tid == 0) {
        asm volatile("mbarrier.arrive.expect_tx.shared::cta.b64 _, [%0], %1;"
                     :: "r"(u_mbar), "r"(TILE_BYTES) : "memory");
        asm volatile(
            "cp.async.bulk.shared::cta.global.mbarrier::complete_tx::bytes "
            "[%0], [%1], %2, [%3];"
            :: "r"(u_tile), "l"(g_dist + base_g), "r"(TILE_BYTES), "r"(u_mbar)
            : "memory");
    }

    // ---- partition rows by mask (overlaps the TMA load) ----
    if (tid < ROWS) {
        const int m = __ldg(g_mask + row0 + tid);
        const int pos = m ? atomicAdd(&s_cnt[0], 1) : atomicSub(&s_cnt[1], 1);
        s_perm[pos] = tid;
        s_mkf[pos]  = (float)m;
    }
    __syncthreads();

    const int   prow = s_perm[slot];               // permuted physical row
    const float mk   = s_mkf[slot];
    const float rw   = __ldg(g_reward + row0 + prow);
    const float step = 0.99f * mk;
    float base = (rw + 10.0f) / 0.4f - 24.75f * mk;      // one div per row
    base = fmaf(step, (float)(half * 25), base);          // shift to atom 25*half
    const float HI = 49.999996f;                          // largest f32 < 50

    // ---- wait for the tile (parity 0) ----
    {
        uint32_t done;
        asm volatile(
            "{\n\t.reg .pred p;\n\t"
            "mbarrier.try_wait.parity.shared::cta.b64 p, [%1], 0;\n\t"
            "selp.b32 %0, 1, 0, p;\n\t}"
            : "=r"(done) : "r"(u_mbar) : "memory");
        while (!done) {
            asm volatile(
                "{\n\t.reg .pred p;\n\t"
                "mbarrier.try_wait.parity.shared::cta.b64 p, [%1], 0, 0x989680;\n\t"
                "selp.b32 %0, 1, 0, p;\n\t}"
                : "=r"(done) : "r"(u_mbar) : "memory");
        }
    }

    // ---- buffer own half-row into registers (stride 51, conflict-free) ----
    float d[HALFN];
    {
        const float* __restrict__ srow = s_tile + prow * ATOMS_C + half * 25;
        #pragma unroll
        for (int j = 0; j < HALFN; ++j) d[j] = srow[j];
        if (half) d[0] = 0.0f;                     // dummy atom 25: zero weight
    }
    __syncthreads();                               // all reads before overwrite

    // ---- cooperative zero of the tile (reused in-place as output) ----
    float4* s4 = reinterpret_cast<float4*>(s_tile);
    const float4 z4 = make_float4(0.f, 0.f, 0.f, 0.f);
    #pragma unroll
    for (int i = 0; i < V4FULL / THREADS; ++i)
        s4[i * THREADS + tid] = z4;
    if (tid < V4REM) s4[V4FULL + tid] = z4;
    __syncthreads();

    // ---- projection ----
    float* __restrict__ orow = s_tile + prow * ATOMS_C;

    float b    = fminf(fmaxf(base, 0.0f), HI);
    float curf = floorf(b);
    float* wptr = orow + (int)curf;                // single F2I per thread
    float acc0, acc1;

    if (mk != 0.0f) {
        // ---- full streaming merge over 26 atoms ----
        acc1 = d[0] * (b - curf);                  // half==1: d[0]=0 -> accs 0
        acc0 = d[0] - acc1;
        #pragma unroll
        for (int j = 1; j < HALFN; ++j) {
            float bb = fmaf(step, (float)j, base); // FFMA, imm multiplier
            bb = fminf(fmaxf(bb, 0.0f), HI);
            const float lfn = floorf(bb);          // independent per atom
            const float bm  = bb - lfn;
            const float wu  = d[j] * bm;
            const float wl  = d[j] - wu;           // d*(lf+1-b)
            const bool adv  = (lfn != curf);       // l steps by exactly 0/1
            if (adv) *wptr = acc0;                 // @P STS, converged
            const float a0 = adv ? acc1 : acc0;
            acc0 = a0 + wl;
            const float t  = acc1 + wu;
            acc1 = adv ? wu : t;
            wptr = adv ? (wptr + 1) : wptr;
            curf = lfn;
        }
    } else {
        // ---- fast path: step==0, all atoms land on the same bin pair ----
        float s01 = 0.f, s23 = 0.f;                // pairwise tree for ILP
        #pragma unroll
        for (int j = 0; j < HALFN; j += 2) { s01 += d[j]; s23 += d[j + 1]; }
        const float s = s01 + s23;
        const float frac = b - curf;
        acc1 = s * frac;
        acc0 = s - acc1;
    }

    if (half) {                                    // B: plain final flush
        wptr[0] = acc0;
        wptr[1] = acc1;
    }
    __syncthreads();
    if (!half) {                                   // A: deferred carry, RMW add
        wptr[0] += acc0;                           // lands in B-written region
        wptr[1] += acc1;
    }

    // ---- TMA bulk store: SMEM -> GMEM ----
    asm volatile("fence.proxy.async.shared::cta;" ::: "memory");
    __syncthreads();
    if (tid == 0) {
        asm volatile(
            "cp.async.bulk.global.shared::cta.bulk_group [%0], [%1], %2;"
            :: "l"(g_out + base_g), "r"(u_tile), "r"(TILE_BYTES) : "memory");
        asm volatile("cp.async.bulk.commit_group;" ::: "memory");
        asm volatile("cp.async.bulk.wait_group 0;" ::: "memory");
    }
}

extern "C" void kernel_launch(void* const* d_in, const int* in_sizes, int n_in,
                              void* d_out, int out_size) {
    const float* reward = (const float*)d_in[0];   // batch_reward  [B] f32
    const float* dist   = (const float*)d_in[1];   // max_next_dist [B,51] f32
    // d_in[2] = supports (linspace) — folded into the affine map, unused
    const int*   mask   = (const int*)d_in[3];     // non_final_mask[B] i32
    float* out = (float*)d_out;                    // [B,51] f32

    const int B = in_sizes[0];                     // 1048576 (divisible by 64)
    const int blocks = B / ROWS;
    c51_project_kernel<<<blocks, THREADS>>>(reward, dist, mask, out);
}

// round 11
// speedup vs baseline: 1.0708x; 1.0074x over previous
#include <cuda_runtime.h>
#include <cstdint>

// C51 categorical projection, round 11.
// R6 merge core (4 threads/row, 32 regs, 256 threads -> 100% theoretical
// occupancy at 8 blocks/SM) fused with R7's TMA bulk stage-in/out (which
// freed the L1 headroom that made R6 regress pre-TMA). Single in-place tile.

static constexpr int ATOMS_C    = 51;
static constexpr int ROWS       = 64;               // rows per block
static constexpr int THREADS    = 256;              // 4 threads per row
static constexpr int TILE       = ROWS * ATOMS_C;   // 3264 floats
static constexpr int TILE_BYTES = TILE * 4;         // 13056
static constexpr int SEG        = 13;               // atoms per segment (last: 12)
static constexpr int V4         = TILE / 4;         // 816
static constexpr int V4FULL     = (V4 / THREADS) * THREADS;  // 768
static constexpr int V4REM      = V4 - V4FULL;               // 48

__global__ __launch_bounds__(THREADS, 8) void c51_project_kernel(
    const float* __restrict__ g_reward,
    const float* __restrict__ g_dist,
    const int*   __restrict__ g_mask,
    float*       __restrict__ g_out)
{
    __shared__ alignas(128) float s_tile[TILE];
    __shared__ alignas(8)  unsigned long long s_mbar;

    const int tid = threadIdx.x;
    const int row = tid & (ROWS - 1);
    const int q   = tid >> 6;                      // segment 0..3 (warp-uniform)
    const long long base_g = (long long)blockIdx.x * TILE;

    const uint32_t u_tile = (uint32_t)__cvta_generic_to_shared(s_tile);
    const uint32_t u_mbar = (uint32_t)__cvta_generic_to_shared(&s_mbar);

    // ---- TMA bulk load: GMEM -> SMEM ----
    if (tid == 0) {
        asm volatile("mbarrier.init.shared::cta.b64 [%0], 1;" :: "r"(u_mbar));
        asm volatile("fence.proxy.async.shared::cta;" ::: "memory");
    }
    __syncthreads();
    if (tid == 0) {
        asm volatile("mbarrier.arrive.expect_tx.shared::cta.b64 _, [%0], %1;"
                     :: "r"(u_mbar), "r"(TILE_BYTES) : "memory");
        asm volatile(
            "cp.async.bulk.shared::cta.global.mbarrier::complete_tx::bytes "
            "[%0], [%1], %2, [%3];"
            :: "r"(u_tile), "l"(g_dist + base_g), "r"(TILE_BYTES), "r"(u_mbar)
            : "memory");
    }

    // ---- Overlap with TMA: per-row affine bin map ----
    const int   s    = q * SEG;                    // first real atom
    const bool  last = (q == 3);
    const int   r    = blockIdx.x * ROWS + row;
    const float rw   = __ldg(g_reward + r);
    const float mk   = (float)__ldg(g_mask + r);
    const float step = 0.99f * mk;
    float base = (rw + 10.0f) / 0.4f - 24.75f * mk;       // one div per row
    base = fmaf(step, (float)(s - 1), base);               // shift to dummy atom
    const float HI = 49.999996f;                            // largest f32 < 50

    // ---- Wait for the tile (parity 0) ----
    {
        uint32_t done;
        asm volatile(
            "{\n\t.reg .pred p;\n\t"
            "mbarrier.try_wait.parity.shared::cta.b64 p, [%1], 0;\n\t"
            "selp.b32 %0, 1, 0, p;\n\t}"
            : "=r"(done) : "r"(u_mbar) : "memory");
        while (!done) {
            asm volatile(
                "{\n\t.reg .pred p;\n\t"
                "mbarrier.try_wait.parity.shared::cta.b64 p, [%1], 0, 0x989680;\n\t"
                "selp.b32 %0, 1, 0, p;\n\t}"
                : "=r"(done) : "r"(u_mbar) : "memory");
        }
    }

    // ---- Buffer segment into registers (stride 51, conflict-free) ----
    float d[SEG + 1];
    {
        const float* __restrict__ srow = s_tile + row * ATOMS_C + (s - 1);
        d[0] = 0.0f;                               // dummy atom s-1: zero weight
        #pragma unroll
        for (int j = 1; j <= SEG; ++j) {
            if (last && j == SEG) d[j] = 0.0f;     // q3 has 12 real atoms
            else                  d[j] = srow[j];  // guarded: no OOB load
        }
    }
    __syncthreads();                               // all reads before overwrite

    // ---- Cooperative zero of the tile (reused in-place as output) ----
    float4* s4 = reinterpret_cast<float4*>(s_tile);
    const float4 z4 = make_float4(0.f, 0.f, 0.f, 0.f);
    #pragma unroll
    for (int i = 0; i < V4FULL / THREADS; ++i)     // 3 rounds of 256
        s4[i * THREADS + tid] = z4;
    if (tid < V4REM) s4[V4FULL + tid] = z4;
    __syncthreads();

    // ---- Streaming merge over dummy + up to 13 real atoms ----
    float* __restrict__ orow = s_tile + row * ATOMS_C;

    float b    = fminf(fmaxf(base, 0.0f), HI);     // dummy: weight 0
    float curf = floorf(b);
    float* wptr = orow + (int)curf;                // single F2I per thread
    float acc0 = 0.0f, acc1 = 0.0f;

    const int L = last ? SEG - 1 : SEG;            // 12 real atoms for q3
    #pragma unroll
    for (int j = 1; j <= SEG; ++j) {
        if (j > L) break;                          // warp-uniform
        float bb = fmaf(step, (float)j, base);     // FFMA, imm multiplier
        bb = fminf(fmaxf(bb, 0.0f), HI);
        const float lfn = floorf(bb);              // independent per atom
        const float bm  = bb - lfn;
        const float wu  = d[j] * bm;
        const float wl  = d[j] - wu;               // d*(lf+1-b)
        const bool adv  = (lfn != curf);           // l steps by exactly 0/1
        if (adv) *wptr = acc0;                     // @P STS, converged
        const float a0 = adv ? acc1 : acc0;
        acc0 = a0 + wl;
        const float t  = acc1 + wu;
        acc1 = adv ? wu : t;
        wptr = adv ? (wptr + 1) : wptr;
        curf = lfn;
    }
    if (last) {                                    // q3: plain finals
        wptr[0] = acc0;                            // curf <= 49
        wptr[1] = acc1;
    }
    __syncthreads();
    if (!last) {                                   // q0-2: carry adds (may
        atomicAdd(&wptr[0], acc0);                 // collide when mask==0)
        atomicAdd(&wptr[1], acc1);
    }

    // ---- TMA bulk store: SMEM -> GMEM ----
    asm volatile("fence.proxy.async.shared::cta;" ::: "memory");
    __syncthreads();
    if (tid == 0) {
        asm volatile(
            "cp.async.bulk.global.shared::cta.bulk_group [%0], [%1], %2;"
            :: "l"(g_out + base_g), "r"(u_tile), "r"(TILE_BYTES) : "memory");
        asm volatile("cp.async.bulk.commit_group;" ::: "memory");
        asm volatile("cp.async.bulk.wait_group 0;" ::: "memory");
    }
}

extern "C" void kernel_launch(void* const* d_in, const int* in_sizes, int n_in,
                              void* d_out, int out_size) {
    const float* reward = (const float*)d_in[0];   // batch_reward  [B] f32
    const float* dist   = (const float*)d_in[1];   // max_next_dist [B,51] f32
    // d_in[2] = supports (linspace) — folded into the affine map, unused
    const int*   mask   = (const int*)d_in[3];     // non_final_mask[B] i32
    float* out = (float*)d_out;                    // [B,51] f32

    const int B = in_sizes[0];                     // 1048576 (divisible by 64)
    const int blocks = B / ROWS;
    c51_project_kernel<<<blocks, THREADS>>>(reward, dist, mask, out);
}

// round 12
// speedup vs baseline: 1.0808x; 1.0093x over previous
#include <cuda_runtime.h>
#include <cstdint>

// C51 categorical projection, round 12.
// R7 algorithm (TMA bulk in/out, 2 threads/row predicated streaming merge,
// single in-place tile) at ROWS=32 / THREADS=64: ~25 resident CTAs per SM
// (vs 12), each carrying one TMA load in flight -> ~2x the tile-stream MLP.
// Resident-CTA count tracked DRAM% across R7/R8/R9/R11; this maximizes it.

static constexpr int ATOMS_C    = 51;
static constexpr int ROWS       = 32;               // rows per block
static constexpr int THREADS    = 64;               // 2 threads per row
static constexpr int TILE       = ROWS * ATOMS_C;   // 1632 floats
static constexpr int TILE_BYTES = TILE * 4;         // 6528 (multiple of 16)
static constexpr int HALFN      = 26;               // atoms per half (incl. dummy)
static constexpr int V4         = TILE / 4;         // 408
static constexpr int V4FULL     = (V4 / THREADS) * THREADS;  // 384
static constexpr int V4REM      = V4 - V4FULL;               // 24

__global__ __launch_bounds__(THREADS) void c51_project_kernel(
    const float* __restrict__ g_reward,
    const float* __restrict__ g_dist,
    const int*   __restrict__ g_mask,
    float*       __restrict__ g_out)
{
    __shared__ alignas(128) float s_tile[TILE];
    __shared__ alignas(8)  unsigned long long s_mbar;

    const int tid  = threadIdx.x;
    const int row  = tid & (ROWS - 1);
    const int half = tid >> 5;                      // warp 0: atoms 0..25, warp 1: 25..50
    const long long base_g = (long long)blockIdx.x * TILE;

    const uint32_t u_tile = (uint32_t)__cvta_generic_to_shared(s_tile);
    const uint32_t u_mbar = (uint32_t)__cvta_generic_to_shared(&s_mbar);

    // ---- TMA bulk load: GMEM -> SMEM, no register round-trip ----
    if (tid == 0) {
        asm volatile("mbarrier.init.shared::cta.b64 [%0], 1;" :: "r"(u_mbar));
        asm volatile("fence.proxy.async.shared::cta;" ::: "memory");
    }
    __syncthreads();
    if (tid == 0) {
        asm volatile("mbarrier.arrive.expect_tx.shared::cta.b64 _, [%0], %1;"
                     :: "r"(u_mbar), "r"(TILE_BYTES) : "memory");
        asm volatile(
            "cp.async.bulk.shared::cta.global.mbarrier::complete_tx::bytes "
            "[%0], [%1], %2, [%3];"
            :: "r"(u_tile), "l"(g_dist + base_g), "r"(TILE_BYTES), "r"(u_mbar)
            : "memory");
    }

    // ---- Overlap with TMA: per-row affine bin map ----
    const int   r    = blockIdx.x * ROWS + row;
    const float rw   = __ldg(g_reward + r);
    const float mk   = (float)__ldg(g_mask + r);
    const float step = 0.99f * mk;
    float base = (rw + 10.0f) / 0.4f - 24.75f * mk;       // one div per row
    base = fmaf(step, (float)(half * 25), base);           // shift to atom 25*half
    const float HI = 49.999996f;                           // largest f32 < 50

    // ---- Wait for the tile (parity 0) ----
    {
        uint32_t done;
        asm volatile(
            "{\n\t.reg .pred p;\n\t"
            "mbarrier.try_wait.parity.shared::cta.b64 p, [%1], 0;\n\t"
            "selp.b32 %0, 1, 0, p;\n\t}"
            : "=r"(done) : "r"(u_mbar) : "memory");
        while (!done) {
            asm volatile(
                "{\n\t.reg .pred p;\n\t"
                "mbarrier.try_wait.parity.shared::cta.b64 p, [%1], 0, 0x989680;\n\t"
                "selp.b32 %0, 1, 0, p;\n\t}"
                : "=r"(done) : "r"(u_mbar) : "memory");
        }
    }

    // ---- Buffer own half-row into registers (conflict-free, stride 51) ----
    float d[HALFN];
    {
        const float* __restrict__ srow = s_tile + row * ATOMS_C + half * 25;
        #pragma unroll
        for (int j = 0; j < HALFN; ++j) d[j] = srow[j];
        if (half) d[0] = 0.0f;                     // dummy atom 25: zero weight
    }
    __syncthreads();                               // all reads before overwrite

    // ---- Cooperative zero of the tile (reused in-place as output) ----
    float4* s4 = reinterpret_cast<float4*>(s_tile);
    const float4 z4 = make_float4(0.f, 0.f, 0.f, 0.f);
    #pragma unroll
    for (int i = 0; i < V4FULL / THREADS; ++i)     // 6 rounds of 64
        s4[i * THREADS + tid] = z4;
    if (tid < V4REM) s4[V4FULL + tid] = z4;
    __syncthreads();

    // ---- Streaming merge over this thread's 26 atoms ----
    float* __restrict__ orow = s_tile + row * ATOMS_C;

    float b    = fminf(fmaxf(base, 0.0f), HI);
    float curf = floorf(b);
    float* wptr = orow + (int)curf;                // single F2I per thread
    float acc1 = d[0] * (b - curf);                // half==1: d[0]=0 -> accs 0
    float acc0 = d[0] - acc1;

    #pragma unroll
    for (int j = 1; j < HALFN; ++j) {
        float bb = fmaf(step, (float)j, base);     // FFMA, imm multiplier
        bb = fminf(fmaxf(bb, 0.0f), HI);
        const float lfn = floorf(bb);              // independent per atom
        const float bm  = bb - lfn;
        const float wu  = d[j] * bm;
        const float wl  = d[j] - wu;               // d*(lf+1-b)
        const bool adv  = (lfn != curf);           // l steps by exactly 0/1
        if (adv) *wptr = acc0;                     // @P STS, converged
        const float a0 = adv ? acc1 : acc0;
        acc0 = a0 + wl;
        const float t  = acc1 + wu;
        acc1 = adv ? wu : t;
        wptr = adv ? (wptr + 1) : wptr;
        curf = lfn;
    }
    if (half) {                                    // B: plain final flush
        wptr[0] = acc0;                            // covers [cA, cB+1] once
        wptr[1] = acc1;
    }
    __syncthreads();
    if (!half) {                                   // A: deferred carry, RMW add
        wptr[0] += acc0;                           // bins [cA, cA+1], B's region
        wptr[1] += acc1;
    }

    // ---- TMA bulk store: SMEM -> GMEM ----
    asm volatile("fence.proxy.async.shared::cta;" ::: "memory");
    __syncthreads();
    if (tid == 0) {
        asm volatile(
            "cp.async.bulk.global.shared::cta.bulk_group [%0], [%1], %2;"
            :: "l"(g_out + base_g), "r"(u_tile), "r"(TILE_BYTES) : "memory");
        asm volatile("cp.async.bulk.commit_group;" ::: "memory");
        asm volatile("cp.async.bulk.wait_group 0;" ::: "memory");
    }
}

extern "C" void kernel_launch(void* const* d_in, const int* in_sizes, int n_in,
                              void* d_out, int out_size) {
    const float* reward = (const float*)d_in[0];   // batch_reward  [B] f32
    const float* dist   = (const float*)d_in[1];   // max_next_dist [B,51] f32
    // d_in[2] = supports (linspace) — folded into the affine map, unused
    const int*   mask   = (const int*)d_in[3];     // non_final_mask[B] i32
    float* out = (float*)d_out;                    // [B,51] f32

    const int B = in_sizes[0];                     // 1048576 (divisible by 32)
    const int blocks = B / ROWS;                   // 32768
    c51_project_kernel<<<blocks, THREADS>>>(reward, dist, mask, out);
}

// round 13
// speedup vs baseline: 1.0874x; 1.0061x over previous
#include <cuda_runtime.h>
#include <cstdint>

// C51 categorical projection, round 13.
// Double-buffered 2-tiles-per-block: both TMA loads are issued at block start;
// tile 1's load latency hides entirely behind tile 0's compute/syncs, and
// tile 0's bulk store drains behind tile 1's compute. Merge core unchanged
// (2 threads/row, predicated streaming merge, in-place tile reuse).

static constexpr int ATOMS_C    = 51;
static constexpr int ROWS       = 32;               // rows per tile
static constexpr int THREADS    = 64;               // 2 threads per row
static constexpr int TILE       = ROWS * ATOMS_C;   // 1632 floats
static constexpr int TILE_BYTES = TILE * 4;         // 6528
static constexpr int HALFN      = 26;               // atoms per half (incl. dummy)
static constexpr int NT         = 2;                // tiles per block
static constexpr int V4         = TILE / 4;         // 408
static constexpr int V4FULL     = (V4 / THREADS) * THREADS;  // 384
static constexpr int V4REM      = V4 - V4FULL;               // 24

__global__ __launch_bounds__(THREADS) void c51_project_kernel(
    const float* __restrict__ g_reward,
    const float* __restrict__ g_dist,
    const int*   __restrict__ g_mask,
    float*       __restrict__ g_out)
{
    __shared__ alignas(128) float s_tile[NT][TILE];
    __shared__ alignas(8)  unsigned long long s_mbar[NT];

    const int tid  = threadIdx.x;
    const int row  = tid & (ROWS - 1);
    const int half = tid >> 5;                      // warp 0 / warp 1

    uint32_t u_tile[NT], u_mbar[NT];
    #pragma unroll
    for (int p = 0; p < NT; ++p) {
        u_tile[p] = (uint32_t)__cvta_generic_to_shared(s_tile[p]);
        u_mbar[p] = (uint32_t)__cvta_generic_to_shared(&s_mbar[p]);
    }

    // ---- init barriers, then issue BOTH loads immediately ----
    if (tid == 0) {
        #pragma unroll
        for (int p = 0; p < NT; ++p)
            asm volatile("mbarrier.init.shared::cta.b64 [%0], 1;" :: "r"(u_mbar[p]));
        asm volatile("fence.proxy.async.shared::cta;" ::: "memory");
    }
    __syncthreads();
    if (tid == 0) {
        #pragma unroll
        for (int p = 0; p < NT; ++p) {
            const long long tg = ((long long)blockIdx.x * NT + p) * TILE;
            asm volatile("mbarrier.arrive.expect_tx.shared::cta.b64 _, [%0], %1;"
                         :: "r"(u_mbar[p]), "r"(TILE_BYTES) : "memory");
            asm volatile(
                "cp.async.bulk.shared::cta.global.mbarrier::complete_tx::bytes "
                "[%0], [%1], %2, [%3];"
                :: "r"(u_tile[p]), "l"(g_dist + tg), "r"(TILE_BYTES),
                   "r"(u_mbar[p]) : "memory");
        }
    }

    const float HI = 49.999996f;                    // largest f32 < 50

    #pragma unroll
    for (int p = 0; p < NT; ++p) {
        const int       t      = blockIdx.x * NT + p;
        const long long base_g = (long long)t * TILE;

        // ---- per-row affine bin map (overlaps the load wait) ----
        const int   r    = t * ROWS + row;
        const float rw   = __ldg(g_reward + r);
        const float mk   = (float)__ldg(g_mask + r);
        const float step = 0.99f * mk;
        float base = (rw + 10.0f) / 0.4f - 24.75f * mk;   // one div per row
        base = fmaf(step, (float)(half * 25), base);       // shift to atom 25*half

        // ---- wait for this tile (parity 0; each barrier used once) ----
        {
            uint32_t done;
            asm volatile(
                "{\n\t.reg .pred q;\n\t"
                "mbarrier.try_wait.parity.shared::cta.b64 q, [%1], 0;\n\t"
                "selp.b32 %0, 1, 0, q;\n\t}"
                : "=r"(done) : "r"(u_mbar[p]) : "memory");
            while (!done) {
                asm volatile(
                    "{\n\t.reg .pred q;\n\t"
                    "mbarrier.try_wait.parity.shared::cta.b64 q, [%1], 0, 0x989680;\n\t"
                    "selp.b32 %0, 1, 0, q;\n\t}"
                    : "=r"(done) : "r"(u_mbar[p]) : "memory");
            }
        }

        float* __restrict__ tile = s_tile[p];

        // ---- buffer own half-row into registers (stride 51, conflict-free) ----
        float d[HALFN];
        {
            const float* __restrict__ srow = tile + row * ATOMS_C + half * 25;
            #pragma unroll
            for (int j = 0; j < HALFN; ++j) d[j] = srow[j];
            if (half) d[0] = 0.0f;                 // dummy atom 25: zero weight
        }
        __syncthreads();                           // all reads before overwrite

        // ---- cooperative zero of the tile (reused in-place as output) ----
        float4* s4 = reinterpret_cast<float4*>(tile);
        const float4 z4 = make_float4(0.f, 0.f, 0.f, 0.f);
        #pragma unroll
        for (int i = 0; i < V4FULL / THREADS; ++i)
            s4[i * THREADS + tid] = z4;
        if (tid < V4REM) s4[V4FULL + tid] = z4;
        __syncthreads();

        // ---- streaming merge over this thread's 26 atoms ----
        float* __restrict__ orow = tile + row * ATOMS_C;

        float b    = fminf(fmaxf(base, 0.0f), HI);
        float curf = floorf(b);
        float* wptr = orow + (int)curf;            // single F2I per thread
        float acc1 = d[0] * (b - curf);            // half==1: d[0]=0 -> accs 0
        float acc0 = d[0] - acc1;

        #pragma unroll
        for (int j = 1; j < HALFN; ++j) {
            float bb = fmaf(step, (float)j, base); // FFMA, imm multiplier
            bb = fminf(fmaxf(bb, 0.0f), HI);
            const float lfn = floorf(bb);          // independent per atom
            const float bm  = bb - lfn;
            const float wu  = d[j] * bm;
            const float wl  = d[j] - wu;           // d*(lf+1-b)
            const bool adv  = (lfn != curf);       // l steps by exactly 0/1
            if (adv) *wptr = acc0;                 // @P STS, converged
            const float a0 = adv ? acc1 : acc0;
            acc0 = a0 + wl;
            const float tt = acc1 + wu;
            acc1 = adv ? wu : tt;
            wptr = adv ? (wptr + 1) : wptr;
            curf = lfn;
        }
        if (half) {                                // B: plain final flush
            wptr[0] = acc0;                        // covers [cA, cB+1] once
            wptr[1] = acc1;
        }
        __syncthreads();
        if (!half) {                               // A: deferred carry, RMW add
            wptr[0] += acc0;                       // bins [cA, cA+1], B's region
            wptr[1] += acc1;
        }

        // ---- bulk store (drains behind the next tile's compute) ----
        asm volatile("fence.proxy.async.shared::cta;" ::: "memory");
        __syncthreads();
        if (tid == 0) {
            asm volatile(
                "cp.async.bulk.global.shared::cta.bulk_group [%0], [%1], %2;"
                :: "l"(g_out + base_g), "r"(u_tile[p]), "r"(TILE_BYTES)
                : "memory");
            asm volatile("cp.async.bulk.commit_group;" ::: "memory");
        }
    }
    if (tid == 0)
        asm volatile("cp.async.bulk.wait_group 0;" ::: "memory");
}

extern "C" void kernel_launch(void* const* d_in, const int* in_sizes, int n_in,
                              void* d_out, int out_size) {
    const float* reward = (const float*)d_in[0];   // batch_reward  [B] f32
    const float* dist   = (const float*)d_in[1];   // max_next_dist [B,51] f32
    // d_in[2] = supports (linspace) — folded into the affine map, unused
    const int*   mask   = (const int*)d_in[3];     // non_final_mask[B] i32
    float* out = (float*)d_out;                    // [B,51] f32

    const int B = in_sizes[0];                     // 1048576
    const int blocks = B / (ROWS * NT);            // 16384
    c51_project_kernel<<<blocks, THREADS>>>(reward, dist, mask, out);
}